// round 7
// baseline (speedup 1.0000x reference)
#include <cuda_runtime.h>
#include <cuda_bf16.h>
#include <math.h>
#include <stdint.h>

#define D_MODEL 1024
#define D_INNER 2048
#define D_STATE 16
#define D_CONV 4
#define DT_RANK 64
#define N_LAYERS 6
#define BATCH 2
#define SEQ 2048
#define T_TOK (BATCH*SEQ)      // 4096 tokens
#define XDBL_W (DT_RANK + 2*D_STATE)   // 96
#define SPLITK 8

// ------------------------- scratch (device globals) -------------------------
__device__ float g_xr  [T_TOK * D_INNER];
__device__ float g_z   [T_TOK * D_INNER];
__device__ float g_xdbl[T_TOK * XDBL_W];
__device__ float g_part[SPLITK * T_TOK * XDBL_W];
__device__ float g_dt  [T_TOK * D_INNER];
__device__ float g_o1  [T_TOK * D_MODEL];
__device__ float g_x   [T_TOK * D_MODEL];

// split bf16 activations (hi/lo)
__device__ __nv_bfloat16 g_xh [T_TOK * D_MODEL],  g_xl [T_TOK * D_MODEL];
__device__ __nv_bfloat16 g_uh [T_TOK * D_INNER],  g_ul [T_TOK * D_INNER];
__device__ __nv_bfloat16 g_yh [T_TOK * D_INNER],  g_yl [T_TOK * D_INNER];
__device__ __nv_bfloat16 g_xdh[T_TOK * XDBL_W],   g_xdl[T_TOK * XDBL_W];

// split bf16 weights (per launch prep)
__device__ __nv_bfloat16 g_ipwh[N_LAYERS*2*D_INNER*D_MODEL], g_ipwl[N_LAYERS*2*D_INNER*D_MODEL];
__device__ __nv_bfloat16 g_xpwh[N_LAYERS*XDBL_W*D_INNER],    g_xpwl[N_LAYERS*XDBL_W*D_INNER];
__device__ __nv_bfloat16 g_dpwh[N_LAYERS*D_INNER*DT_RANK],   g_dpwl[N_LAYERS*D_INNER*DT_RANK];
__device__ __nv_bfloat16 g_opwh[N_LAYERS*D_MODEL*D_INNER],   g_opwl[N_LAYERS*D_MODEL*D_INNER];

// --------------------------- bf16 split helpers -----------------------------
__device__ __forceinline__ uint32_t pack_hi(float x0, float x1) {
    return (__float_as_uint(x1) & 0xFFFF0000u) | (__float_as_uint(x0) >> 16);
}
__device__ __forceinline__ uint32_t pack_lo(float x0, float x1) {
    float h0 = __uint_as_float(__float_as_uint(x0) & 0xFFFF0000u);
    float h1 = __uint_as_float(__float_as_uint(x1) & 0xFFFF0000u);
    __nv_bfloat162 t = __floats2bfloat162_rn(x0 - h0, x1 - h1);
    return *(uint32_t*)&t;
}
__device__ __forceinline__ void split1(float v, __nv_bfloat16* hi, __nv_bfloat16* lo) {
    uint16_t hb = (uint16_t)(__float_as_uint(v) >> 16);
    *(uint16_t*)hi = hb;
    float hf = __uint_as_float((uint32_t)hb << 16);
    *lo = __float2bfloat16(v - hf);
}

__device__ __forceinline__ void mma_bf16(float d[4], const uint32_t a[4],
                                         const uint32_t b[2]) {
    asm volatile(
        "mma.sync.aligned.m16n8k16.row.col.f32.bf16.bf16.f32 "
        "{%0,%1,%2,%3}, {%4,%5,%6,%7}, {%8,%9}, {%0,%1,%2,%3};\n"
        : "+f"(d[0]), "+f"(d[1]), "+f"(d[2]), "+f"(d[3])
        : "r"(a[0]), "r"(a[1]), "r"(a[2]), "r"(a[3]), "r"(b[0]), "r"(b[1]));
}

#define LDSM_X4(r, addr) \
    asm volatile("ldmatrix.sync.aligned.m8n8.x4.shared.b16 {%0,%1,%2,%3}, [%4];" \
        : "=r"((r)[0]), "=r"((r)[1]), "=r"((r)[2]), "=r"((r)[3]) : "r"(addr))

__device__ __forceinline__ void cpasync16(uint32_t dst, const void* src, int sz) {
    asm volatile("cp.async.cg.shared.global [%0], [%1], 16, %2;\n"
                 :: "r"(dst), "l"(src), "r"(sz) : "memory");
}
#define CP_COMMIT() asm volatile("cp.async.commit_group;\n" ::: "memory")
#define CP_WAIT0()  asm volatile("cp.async.wait_group 0;\n" ::: "memory")
#define CP_WAIT1()  asm volatile("cp.async.wait_group 1;\n" ::: "memory")

__device__ __forceinline__ uint32_t smaddr(const void* p) {
    uint32_t a;
    asm("{ .reg .u64 t; cvta.to.shared.u64 t, %1; cvt.u32.u64 %0, t; }"
        : "=r"(a) : "l"(p));
    return a;
}

// ================== warp-mma bf16x3 GEMM (all GEMMs) ========================
// C[M,N] = A[M,K(lda)] @ W[N,K]^T. A/W pre-split bf16 hi/lo. 128x128 tile,
// BK=32, 256 thr (4Mx2N warps, 32x64 warp tile), 3-stage cp.async pipeline
// (prefetch distance 2, ONE __syncthreads per K-tile), ldmatrix fragments,
// 3-term compensated bf16 m16n8k16 MMA. Split-K via blockIdx.z.
enum { EPI_NONE = 0, EPI_SPLIT = 1, EPI_SOFTPLUS = 2 };

#define SROW 80                      // smem row stride bytes (64 data + 16 pad)
#define SARR 10240                   // per-matrix smem bytes (128*80)
#define SSTAGE 40960                 // 4 matrices per stage
#define NSTAGE 3
#define SMEM_GEMM (NSTAGE*SSTAGE)    // 122880

template<int EPI>
__global__ __launch_bounds__(256, 1)
void tgemm2(const __nv_bfloat16* __restrict__ Agh, const __nv_bfloat16* __restrict__ Agl,
            int lda,
            const __nv_bfloat16* __restrict__ Wgh, const __nv_bfloat16* __restrict__ Wgl,
            float* __restrict__ C0, float* __restrict__ C1,
            const float* __restrict__ bias,
            int M, int N, int K, int ldc, int kPerSplit)
{
    extern __shared__ uint8_t smraw[];
    uint32_t sm0 = smaddr(smraw);

    const int tid  = threadIdx.x;
    const int lane = tid & 31;
    const int wid  = tid >> 5;
    const int warpM = wid & 3;
    const int warpN = wid >> 2;
    const int grp  = lane >> 2;
    const int tig  = lane & 3;

    const int rowBlock = blockIdx.y * 128;
    const int colBlock = blockIdx.x * 128;
    const int ks = blockIdx.z * kPerSplit;
    const int ntk = kPerSplit / 32;

    float acc[2][8][4];
    #pragma unroll
    for (int mt = 0; mt < 2; mt++)
        #pragma unroll
        for (int nt = 0; nt < 8; nt++)
            #pragma unroll
            for (int q = 0; q < 4; q++) acc[mt][nt][q] = 0.f;

    int lrow[2], lch[2];
    #pragma unroll
    for (int j = 0; j < 2; j++) { int idx = tid + j*256; lrow[j] = idx >> 2; lch[j] = idx & 3; }

    const uint32_t aOffBase = (uint32_t)((warpM*32 + (lane & 15)) * SROW + (lane >> 4) * 16);
    const uint32_t wOffBase = (uint32_t)(2*SARR +
        (warpN*64 + (lane & 7) + ((lane >> 4) & 1) * 8) * SROW + ((lane >> 3) & 1) * 16);

    auto load_tile = [&](int stage, int k0) {
        uint32_t sb = sm0 + stage * SSTAGE;
        #pragma unroll
        for (int j = 0; j < 2; j++) {
            int row = lrow[j], ch = lch[j];
            uint32_t so = (uint32_t)(row * SROW + ch * 16);
            size_t aoff = (size_t)(rowBlock + row) * lda + k0 + ch * 8;
            cpasync16(sb + so,          Agh + aoff, 16);
            cpasync16(sb + SARR + so,   Agl + aoff, 16);
            int wrow = colBlock + row;
            int sz = (wrow < N) ? 16 : 0;
            size_t woff = (wrow < N) ? ((size_t)wrow * K + k0 + ch * 8) : 0;
            cpasync16(sb + 2*SARR + so, Wgh + woff, 16);   // sz handled below
            cpasync16(sb + 3*SARR + so, Wgl + woff, sz);
        }
        CP_COMMIT();
    };
    // NOTE on W hi zfill: re-issue with size guard (keep both hi/lo guarded)
    auto load_tile_g = [&](int stage, int k0) {
        uint32_t sb = sm0 + stage * SSTAGE;
        #pragma unroll
        for (int j = 0; j < 2; j++) {
            int row = lrow[j], ch = lch[j];
            uint32_t so = (uint32_t)(row * SROW + ch * 16);
            size_t aoff = (size_t)(rowBlock + row) * lda + k0 + ch * 8;
            cpasync16(sb + so,          Agh + aoff, 16);
            cpasync16(sb + SARR + so,   Agl + aoff, 16);
            int wrow = colBlock + row;
            int sz = (wrow < N) ? 16 : 0;
            size_t woff = (wrow < N) ? ((size_t)wrow * K + k0 + ch * 8) : 0;
            cpasync16(sb + 2*SARR + so, Wgh + woff, sz);
            cpasync16(sb + 3*SARR + so, Wgl + woff, sz);
        }
        CP_COMMIT();
    };
    (void)load_tile;

    // prologue: prefetch slabs 0 and 1
    load_tile_g(0, ks);
    if (ntk > 1) load_tile_g(1, ks + 32);

    int stage = 0;
    for (int t = 0; t < ntk; t++) {
        if (t + 1 < ntk) { CP_WAIT1(); } else { CP_WAIT0(); }
        __syncthreads();                 // publish stage t; fence compute(t-1)
        if (t + 2 < ntk) {
            int s2 = stage + 2; if (s2 >= NSTAGE) s2 -= NSTAGE;
            load_tile_g(s2, ks + (t + 2) * 32);
        }

        uint32_t sb = sm0 + stage * SSTAGE;
        #pragma unroll
        for (int kk = 0; kk < 2; kk++) {
            uint32_t a_h[2][4], a_l[2][4];
            #pragma unroll
            for (int mt = 0; mt < 2; mt++) {
                uint32_t ad = sb + aOffBase + (uint32_t)(mt * 16 * SROW) + kk * 32;
                LDSM_X4(a_h[mt], ad);
                LDSM_X4(a_l[mt], ad + SARR);
            }
            #pragma unroll
            for (int ng = 0; ng < 4; ng++) {
                uint32_t wd = sb + wOffBase + (uint32_t)(ng * 16 * SROW) + kk * 32;
                uint32_t b_h[4], b_l[4];
                LDSM_X4(b_h, wd);
                LDSM_X4(b_l, wd + SARR);
                #pragma unroll
                for (int p = 0; p < 2; p++) {
                    int nt = ng * 2 + p;
                    #pragma unroll
                    for (int mt = 0; mt < 2; mt++) {
                        mma_bf16(acc[mt][nt], a_h[mt], &b_h[2*p]);
                        mma_bf16(acc[mt][nt], a_h[mt], &b_l[2*p]);
                        mma_bf16(acc[mt][nt], a_l[mt], &b_h[2*p]);
                    }
                }
            }
        }
        if (++stage == NSTAGE) stage = 0;
    }

    float* Cz = C0 + (size_t)blockIdx.z * ((size_t)M * ldc);
    #pragma unroll
    for (int mt = 0; mt < 2; mt++) {
        #pragma unroll
        for (int nt = 0; nt < 8; nt++) {
            int c = colBlock + warpN * 64 + nt * 8 + tig * 2;
            if (c >= N) continue;
            #pragma unroll
            for (int half = 0; half < 2; half++) {
                int r = rowBlock + warpM * 32 + mt * 16 + grp + half * 8;
                float v0 = acc[mt][nt][half * 2 + 0];
                float v1 = acc[mt][nt][half * 2 + 1];
                if (EPI == EPI_SOFTPLUS) {
                    v0 += bias[c];
                    v1 += bias[c + 1];
                    v0 = (v0 > 0.f) ? (v0 + log1pf(expf(-v0))) : log1pf(expf(v0));
                    v1 = (v1 > 0.f) ? (v1 + log1pf(expf(-v1))) : log1pf(expf(v1));
                }
                if (EPI == EPI_SPLIT) {
                    float* dst = (c < D_INNER)
                        ? (C0 + (size_t)r * ldc + c)
                        : (C1 + (size_t)r * ldc + (c - D_INNER));
                    *(float2*)dst = make_float2(v0, v1);
                } else {
                    *(float2*)(Cz + (size_t)r * ldc + c) = make_float2(v0, v1);
                }
            }
        }
    }
}

// --------------------------- weight/src split -------------------------------
__global__ void split_kernel(const float* __restrict__ in,
                             uint32_t* __restrict__ hi, uint32_t* __restrict__ lo,
                             int npairs)
{
    int i = blockIdx.x * 256 + threadIdx.x;
    if (i >= npairs) return;
    float2 v = ((const float2*)in)[i];
    hi[i] = pack_hi(v.x, v.y);
    lo[i] = pack_lo(v.x, v.y);
}

// ------------------------- split-K reduction -------------------------------
__global__ void reduce_part_kernel()
{
    int i = blockIdx.x * 256 + threadIdx.x;
    if (i >= T_TOK * XDBL_W) return;
    float s = 0.f;
    #pragma unroll
    for (int z = 0; z < SPLITK; z++) s += g_part[(size_t)z * (T_TOK*XDBL_W) + i];
    g_xdbl[i] = s;
    split1(s, &g_xdh[i], &g_xdl[i]);
}

// --------------------- causal depthwise conv + silu ------------------------
__global__ void conv_silu_kernel(const float* __restrict__ cw,
                                 const float* __restrict__ cb)
{
    int idx = blockIdx.x * 256 + threadIdx.x;
    if (idx >= T_TOK * D_INNER) return;
    int d = idx % D_INNER;
    int t = idx / D_INNER;
    int b = t / SEQ, s = t % SEQ;
    float w0 = cw[d*4+0], w1 = cw[d*4+1], w2 = cw[d*4+2], w3 = cw[d*4+3];
    const float* col = g_xr + (size_t)(b*SEQ) * D_INNER + d;
    float acc = cb[d];
    if (s >= 3) acc = fmaf(col[(size_t)(s-3)*D_INNER], w0, acc);
    if (s >= 2) acc = fmaf(col[(size_t)(s-2)*D_INNER], w1, acc);
    if (s >= 1) acc = fmaf(col[(size_t)(s-1)*D_INNER], w2, acc);
    acc = fmaf(col[(size_t)s*D_INNER], w3, acc);
    float u = acc / (1.f + expf(-acc));   // silu
    split1(u, &g_uh[idx], &g_ul[idx]);    // fp32 u dropped; consumers use hi+lo
}

// ------------------------------ selective scan ------------------------------
#define SCH 16
#define SST 64
__global__ __launch_bounds__(256)
void scan_kernel(const float* __restrict__ A_log, const float* __restrict__ Dp)
{
    const int b = blockIdx.y;
    const int d_base = blockIdx.x * SCH;
    const int tid = threadIdx.x;
    const int ch = tid >> 4;
    const int n  = tid & 15;
    const int d  = d_base + ch;

    __shared__ float s_dt[SST][SCH];
    __shared__ float s_u [SST][SCH];
    __shared__ float s_B [SST][D_STATE];
    __shared__ float s_C [SST][D_STATE];
    __shared__ float s_y [SST][SCH];

    const float a = -expf(A_log[(size_t)d * D_STATE + n]);
    float h = 0.f;

    for (int s0 = 0; s0 < SEQ; s0 += SST) {
        for (int i = tid; i < SST*SCH; i += 256) {
            int st = i >> 4, c = i & 15;
            size_t off = (size_t)(b*SEQ + s0 + st) * D_INNER + d_base + c;
            s_dt[st][c] = g_dt[off];
            s_u [st][c] = __bfloat162float(g_uh[off]) + __bfloat162float(g_ul[off]);
        }
        for (int i = tid; i < SST*D_STATE; i += 256) {
            int st = i >> 4, nn = i & 15;
            const float* row = g_xdbl + (size_t)(b*SEQ + s0 + st) * XDBL_W;
            s_B[st][nn] = row[DT_RANK + nn];
            s_C[st][nn] = row[DT_RANK + D_STATE + nn];
        }
        __syncthreads();

        #pragma unroll 4
        for (int st = 0; st < SST; st++) {
            float dtv = s_dt[st][ch];
            float da  = __expf(dtv * a);
            float xb  = dtv * s_u[st][ch] * s_B[st][n];
            h = fmaf(da, h, xb);
            float yv = h * s_C[st][n];
            yv += __shfl_xor_sync(0xffffffffu, yv, 8, 16);
            yv += __shfl_xor_sync(0xffffffffu, yv, 4, 16);
            yv += __shfl_xor_sync(0xffffffffu, yv, 2, 16);
            yv += __shfl_xor_sync(0xffffffffu, yv, 1, 16);
            if (n == 0) s_y[st][ch] = yv;
        }
        __syncthreads();

        for (int i = tid; i < SST*SCH; i += 256) {
            int st = i >> 4, c = i & 15;
            size_t off = (size_t)(b*SEQ + s0 + st) * D_INNER + d_base + c;
            float zz = g_z[off];
            float sz = zz / (1.f + __expf(-zz));
            float yy = fmaf(Dp[d_base + c], s_u[st][c], s_y[st][c]) * sz;
            split1(yy, &g_yh[off], &g_yl[off]);
        }
        __syncthreads();
    }
}

// ------------------------------ layernorm ----------------------------------
__global__ __launch_bounds__(256)
void ln_kernel(const float* __restrict__ in, const float* __restrict__ w,
               const float* __restrict__ bb, float* __restrict__ out,
               int write_f32)
{
    const int t = blockIdx.x;
    const int tid = threadIdx.x;
    float4 v = ((const float4*)(in + (size_t)t * D_MODEL))[tid];
    __shared__ float red[9];

    float s = v.x + v.y + v.z + v.w;
    #pragma unroll
    for (int o = 16; o; o >>= 1) s += __shfl_xor_sync(~0u, s, o);
    if ((tid & 31) == 0) red[tid >> 5] = s;
    __syncthreads();
    if (tid == 0) {
        float tot = 0.f;
        #pragma unroll
        for (int i = 0; i < 8; i++) tot += red[i];
        red[8] = tot * (1.f / D_MODEL);
    }
    __syncthreads();
    const float mean = red[8];

    float dx0 = v.x - mean, dx1 = v.y - mean, dx2 = v.z - mean, dx3 = v.w - mean;
    float q = dx0*dx0 + dx1*dx1 + dx2*dx2 + dx3*dx3;
    #pragma unroll
    for (int o = 16; o; o >>= 1) q += __shfl_xor_sync(~0u, q, o);
    __syncthreads();
    if ((tid & 31) == 0) red[tid >> 5] = q;
    __syncthreads();
    if (tid == 0) {
        float tot = 0.f;
        #pragma unroll
        for (int i = 0; i < 8; i++) tot += red[i];
        red[8] = rsqrtf(tot * (1.f / D_MODEL) + 1e-5f);
    }
    __syncthreads();
    const float inv = red[8];

    float4 wv = ((const float4*)w)[tid];
    float4 bv = ((const float4*)bb)[tid];
    float4 o;
    o.x = fmaf(dx0 * inv, wv.x, bv.x);
    o.y = fmaf(dx1 * inv, wv.y, bv.y);
    o.z = fmaf(dx2 * inv, wv.z, bv.z);
    o.w = fmaf(dx3 * inv, wv.w, bv.w);
    if (write_f32)
        ((float4*)(out + (size_t)t * D_MODEL))[tid] = o;

    int pidx = t * (D_MODEL/2) + tid * 2;
    ((uint32_t*)g_xh)[pidx]     = pack_hi(o.x, o.y);
    ((uint32_t*)g_xh)[pidx + 1] = pack_hi(o.z, o.w);
    ((uint32_t*)g_xl)[pidx]     = pack_lo(o.x, o.y);
    ((uint32_t*)g_xl)[pidx + 1] = pack_lo(o.z, o.w);
}

// ------------------------------ decoder ------------------------------------
__global__ void dec_kernel(const float* __restrict__ x,
                           const float* __restrict__ dw,
                           const float* __restrict__ db,
                           float* __restrict__ out)
{
    int warp = (blockIdx.x * blockDim.x + threadIdx.x) >> 5;
    int lane = threadIdx.x & 31;
    if (warp >= T_TOK) return;
    const float* row = x + (size_t)warp * D_MODEL;
    float s = 0.f;
    for (int k = lane; k < D_MODEL; k += 32) s = fmaf(row[k], dw[k], s);
    #pragma unroll
    for (int o = 16; o; o >>= 1) s += __shfl_xor_sync(~0u, s, o);
    if (lane == 0) out[warp] = 1.f / (1.f + expf(-(s + db[0])));
}

// ------------------------------ launcher -----------------------------------
extern "C" void kernel_launch(void* const* d_in, const int* in_sizes, int n_in,
                              void* d_out, int out_size)
{
    const float* source = (const float*)d_in[0];
    const float* ipw    = (const float*)d_in[1];
    const float* cw     = (const float*)d_in[2];
    const float* cb     = (const float*)d_in[3];
    const float* xpw    = (const float*)d_in[4];
    const float* dpw    = (const float*)d_in[5];
    const float* dpb    = (const float*)d_in[6];
    const float* alog   = (const float*)d_in[7];
    const float* Dp     = (const float*)d_in[8];
    const float* opw    = (const float*)d_in[9];
    const float* lnw    = (const float*)d_in[10];
    const float* lnb    = (const float*)d_in[11];
    const float* dw     = (const float*)d_in[12];
    const float* db     = (const float*)d_in[13];
    float* out = (float*)d_out;

    float *p_xr, *p_z, *p_xdbl, *p_dt, *p_o1, *p_x, *p_part;
    cudaGetSymbolAddress((void**)&p_xr,   g_xr);
    cudaGetSymbolAddress((void**)&p_z,    g_z);
    cudaGetSymbolAddress((void**)&p_xdbl, g_xdbl);
    cudaGetSymbolAddress((void**)&p_dt,   g_dt);
    cudaGetSymbolAddress((void**)&p_o1,   g_o1);
    cudaGetSymbolAddress((void**)&p_x,    g_x);
    cudaGetSymbolAddress((void**)&p_part, g_part);

    __nv_bfloat16 *p_xh, *p_xl, *p_uh, *p_ul, *p_yh, *p_yl, *p_xdh, *p_xdl;
    cudaGetSymbolAddress((void**)&p_xh,  g_xh);
    cudaGetSymbolAddress((void**)&p_xl,  g_xl);
    cudaGetSymbolAddress((void**)&p_uh,  g_uh);
    cudaGetSymbolAddress((void**)&p_ul,  g_ul);
    cudaGetSymbolAddress((void**)&p_yh,  g_yh);
    cudaGetSymbolAddress((void**)&p_yl,  g_yl);
    cudaGetSymbolAddress((void**)&p_xdh, g_xdh);
    cudaGetSymbolAddress((void**)&p_xdl, g_xdl);

    __nv_bfloat16 *p_ipwh, *p_ipwl, *p_xpwh, *p_xpwl, *p_dpwh, *p_dpwl, *p_opwh, *p_opwl;
    cudaGetSymbolAddress((void**)&p_ipwh, g_ipwh);
    cudaGetSymbolAddress((void**)&p_ipwl, g_ipwl);
    cudaGetSymbolAddress((void**)&p_xpwh, g_xpwh);
    cudaGetSymbolAddress((void**)&p_xpwl, g_xpwl);
    cudaGetSymbolAddress((void**)&p_dpwh, g_dpwh);
    cudaGetSymbolAddress((void**)&p_dpwl, g_dpwl);
    cudaGetSymbolAddress((void**)&p_opwh, g_opwh);
    cudaGetSymbolAddress((void**)&p_opwl, g_opwl);

    cudaFuncSetAttribute(tgemm2<EPI_SPLIT>,    cudaFuncAttributeMaxDynamicSharedMemorySize, SMEM_GEMM);
    cudaFuncSetAttribute(tgemm2<EPI_NONE>,     cudaFuncAttributeMaxDynamicSharedMemorySize, SMEM_GEMM);
    cudaFuncSetAttribute(tgemm2<EPI_SOFTPLUS>, cudaFuncAttributeMaxDynamicSharedMemorySize, SMEM_GEMM);

    // per-launch weight + source splits
    {
        int np;
        np = N_LAYERS*2*D_INNER*D_MODEL/2;
        split_kernel<<<(np+255)/256, 256>>>(ipw, (uint32_t*)p_ipwh, (uint32_t*)p_ipwl, np);
        np = N_LAYERS*XDBL_W*D_INNER/2;
        split_kernel<<<(np+255)/256, 256>>>(xpw, (uint32_t*)p_xpwh, (uint32_t*)p_xpwl, np);
        np = N_LAYERS*D_INNER*DT_RANK/2;
        split_kernel<<<(np+255)/256, 256>>>(dpw, (uint32_t*)p_dpwh, (uint32_t*)p_dpwl, np);
        np = N_LAYERS*D_MODEL*D_INNER/2;
        split_kernel<<<(np+255)/256, 256>>>(opw, (uint32_t*)p_opwh, (uint32_t*)p_opwl, np);
        np = T_TOK*D_MODEL/2;
        split_kernel<<<(np+255)/256, 256>>>(source, (uint32_t*)p_xh, (uint32_t*)p_xl, np);
    }

    for (int i = 0; i < N_LAYERS; i++) {
        // 1) xz = x @ in_proj^T -> (xr | z)
        tgemm2<EPI_SPLIT><<<dim3(32, 32, 1), 256, SMEM_GEMM>>>(
            p_xh, p_xl, D_MODEL,
            p_ipwh + (size_t)i * 2*D_INNER*D_MODEL, p_ipwl + (size_t)i * 2*D_INNER*D_MODEL,
            p_xr, p_z, nullptr,
            T_TOK, 2*D_INNER, D_MODEL, D_INNER, D_MODEL);

        // 2) causal depthwise conv + bias + silu -> uh/ul
        conv_silu_kernel<<<(T_TOK*D_INNER)/256, 256>>>(
            cw + (size_t)i * D_INNER * D_CONV, cb + (size_t)i * D_INNER);

        // 3) x_dbl = u @ x_proj^T (N=96, split-K=8) + reduce (+split)
        tgemm2<EPI_NONE><<<dim3(1, 32, SPLITK), 256, SMEM_GEMM>>>(
            p_uh, p_ul, D_INNER,
            p_xpwh + (size_t)i * XDBL_W * D_INNER, p_xpwl + (size_t)i * XDBL_W * D_INNER,
            p_part, nullptr, nullptr,
            T_TOK, XDBL_W, D_INNER, XDBL_W, D_INNER / SPLITK);
        reduce_part_kernel<<<(T_TOK*XDBL_W + 255)/256, 256>>>();

        // 4) dt = softplus(dt_in @ dt_proj^T + dt_bias)
        tgemm2<EPI_SOFTPLUS><<<dim3(16, 32, 1), 256, SMEM_GEMM>>>(
            p_xdh, p_xdl, XDBL_W,
            p_dpwh + (size_t)i * D_INNER * DT_RANK, p_dpwl + (size_t)i * D_INNER * DT_RANK,
            p_dt, nullptr, dpb + (size_t)i * D_INNER,
            T_TOK, D_INNER, DT_RANK, D_INNER, DT_RANK);

        // 5) selective scan (+ D*u, * silu(z), split output)
        scan_kernel<<<dim3(D_INNER / SCH, BATCH), 256>>>(
            alog + (size_t)i * D_INNER * D_STATE, Dp + (size_t)i * D_INNER);

        // 6) out = y @ out_proj^T
        tgemm2<EPI_NONE><<<dim3(8, 32, 1), 256, SMEM_GEMM>>>(
            p_yh, p_yl, D_INNER,
            p_opwh + (size_t)i * D_MODEL * D_INNER, p_opwl + (size_t)i * D_MODEL * D_INNER,
            p_o1, nullptr, nullptr,
            T_TOK, D_MODEL, D_INNER, D_MODEL, D_INNER);

        // 7) layernorm -> xh/xl (+ fp32 g_x only on last layer for decoder)
        ln_kernel<<<T_TOK, 256>>>(p_o1, lnw + (size_t)i * D_MODEL,
                                  lnb + (size_t)i * D_MODEL, p_x,
                                  (i == N_LAYERS - 1) ? 1 : 0);
    }

    dec_kernel<<<(T_TOK * 32) / 256, 256>>>(p_x, dw, db, out);
}

// round 8
// speedup vs baseline: 1.1058x; 1.1058x over previous
#include <cuda_runtime.h>
#include <cuda_bf16.h>
#include <math.h>
#include <stdint.h>

#define D_MODEL 1024
#define D_INNER 2048
#define D_STATE 16
#define D_CONV 4
#define DT_RANK 64
#define N_LAYERS 6
#define BATCH 2
#define SEQ 2048
#define T_TOK (BATCH*SEQ)      // 4096 tokens
#define XDBL_W (DT_RANK + 2*D_STATE)   // 96
#define SPLITK 8

// ------------------------- scratch (device globals) -------------------------
__device__ float g_xr  [T_TOK * D_INNER];
__device__ float g_z   [T_TOK * D_INNER];
__device__ float g_xdbl[T_TOK * XDBL_W];
__device__ float g_part[SPLITK * T_TOK * XDBL_W];
__device__ float g_dt  [T_TOK * D_INNER];
__device__ float g_o1  [T_TOK * D_MODEL];
__device__ float g_x   [T_TOK * D_MODEL];

// split bf16 activations (hi/lo)
__device__ __nv_bfloat16 g_xh [T_TOK * D_MODEL],  g_xl [T_TOK * D_MODEL];
__device__ __nv_bfloat16 g_uh [T_TOK * D_INNER],  g_ul [T_TOK * D_INNER];
__device__ __nv_bfloat16 g_yh [T_TOK * D_INNER],  g_yl [T_TOK * D_INNER];
__device__ __nv_bfloat16 g_xdh[T_TOK * XDBL_W],   g_xdl[T_TOK * XDBL_W];

// split bf16 weights (per launch prep)
__device__ __nv_bfloat16 g_ipwh[N_LAYERS*2*D_INNER*D_MODEL], g_ipwl[N_LAYERS*2*D_INNER*D_MODEL];
__device__ __nv_bfloat16 g_xpwh[N_LAYERS*XDBL_W*D_INNER],    g_xpwl[N_LAYERS*XDBL_W*D_INNER];
__device__ __nv_bfloat16 g_dpwh[N_LAYERS*D_INNER*DT_RANK],   g_dpwl[N_LAYERS*D_INNER*DT_RANK];
__device__ __nv_bfloat16 g_opwh[N_LAYERS*D_MODEL*D_INNER],   g_opwl[N_LAYERS*D_MODEL*D_INNER];

// --------------------------- bf16 split helpers -----------------------------
__device__ __forceinline__ uint32_t pack_hi(float x0, float x1) {
    return (__float_as_uint(x1) & 0xFFFF0000u) | (__float_as_uint(x0) >> 16);
}
__device__ __forceinline__ uint32_t pack_lo(float x0, float x1) {
    float h0 = __uint_as_float(__float_as_uint(x0) & 0xFFFF0000u);
    float h1 = __uint_as_float(__float_as_uint(x1) & 0xFFFF0000u);
    __nv_bfloat162 t = __floats2bfloat162_rn(x0 - h0, x1 - h1);
    return *(uint32_t*)&t;
}
__device__ __forceinline__ void split1(float v, __nv_bfloat16* hi, __nv_bfloat16* lo) {
    uint16_t hb = (uint16_t)(__float_as_uint(v) >> 16);
    *(uint16_t*)hi = hb;
    float hf = __uint_as_float((uint32_t)hb << 16);
    *lo = __float2bfloat16(v - hf);
}

__device__ __forceinline__ void mma_bf16(float d[4], const uint32_t a[4],
                                         const uint32_t b[2]) {
    asm volatile(
        "mma.sync.aligned.m16n8k16.row.col.f32.bf16.bf16.f32 "
        "{%0,%1,%2,%3}, {%4,%5,%6,%7}, {%8,%9}, {%0,%1,%2,%3};\n"
        : "+f"(d[0]), "+f"(d[1]), "+f"(d[2]), "+f"(d[3])
        : "r"(a[0]), "r"(a[1]), "r"(a[2]), "r"(a[3]), "r"(b[0]), "r"(b[1]));
}

#define LDSM_X4(r, addr) \
    asm volatile("ldmatrix.sync.aligned.m8n8.x4.shared.b16 {%0,%1,%2,%3}, [%4];" \
        : "=r"((r)[0]), "=r"((r)[1]), "=r"((r)[2]), "=r"((r)[3]) : "r"(addr))

__device__ __forceinline__ void cpasync16(uint32_t dst, const void* src, int sz) {
    asm volatile("cp.async.cg.shared.global [%0], [%1], 16, %2;\n"
                 :: "r"(dst), "l"(src), "r"(sz) : "memory");
}
#define CP_COMMIT() asm volatile("cp.async.commit_group;\n" ::: "memory")
#define CP_WAIT0()  asm volatile("cp.async.wait_group 0;\n" ::: "memory")
#define CP_WAIT1()  asm volatile("cp.async.wait_group 1;\n" ::: "memory")

__device__ __forceinline__ uint32_t smaddr(const void* p) {
    uint32_t a;
    asm("{ .reg .u64 t; cvta.to.shared.u64 t, %1; cvt.u32.u64 %0, t; }"
        : "=r"(a) : "l"(p));
    return a;
}

// ================== warp-mma bf16x3 GEMM (R4 config: 2-stage, occ 2) ========
// C[M,N] = A[M,K(lda)] @ W[N,K]^T. A/W pre-split bf16 hi/lo. 128x128 tile,
// BK=32, 256 thr (4Mx2N warps, 32x64 warp tile), 2-stage cp.async pipeline,
// ldmatrix fragments, 3-term compensated bf16 m16n8k16 MMA. Split-K via z.
enum { EPI_NONE = 0, EPI_SPLIT = 1, EPI_SOFTPLUS = 2 };

#define SROW 80                      // smem row stride bytes (64 data + 16 pad)
#define SARR 10240                   // per-matrix smem bytes (128*80)
#define SSTAGE 40960                 // 4 matrices per stage
#define SMEM_GEMM (2*SSTAGE)         // 81920 -> 2 CTAs/SM

template<int EPI>
__global__ __launch_bounds__(256, 2)
void tgemm2(const __nv_bfloat16* __restrict__ Agh, const __nv_bfloat16* __restrict__ Agl,
            int lda,
            const __nv_bfloat16* __restrict__ Wgh, const __nv_bfloat16* __restrict__ Wgl,
            float* __restrict__ C0, float* __restrict__ C1,
            const float* __restrict__ bias,
            int M, int N, int K, int ldc, int kPerSplit)
{
    extern __shared__ uint8_t smraw[];
    uint32_t sm0 = smaddr(smraw);

    const int tid  = threadIdx.x;
    const int lane = tid & 31;
    const int wid  = tid >> 5;
    const int warpM = wid & 3;
    const int warpN = wid >> 2;
    const int grp  = lane >> 2;
    const int tig  = lane & 3;

    const int rowBlock = blockIdx.y * 128;
    const int colBlock = blockIdx.x * 128;
    const int ks = blockIdx.z * kPerSplit;
    const int ntk = kPerSplit / 32;

    float acc[2][8][4];
    #pragma unroll
    for (int mt = 0; mt < 2; mt++)
        #pragma unroll
        for (int nt = 0; nt < 8; nt++)
            #pragma unroll
            for (int q = 0; q < 4; q++) acc[mt][nt][q] = 0.f;

    int lrow[2], lch[2];
    #pragma unroll
    for (int j = 0; j < 2; j++) { int idx = tid + j*256; lrow[j] = idx >> 2; lch[j] = idx & 3; }

    const uint32_t aOffBase = (uint32_t)((warpM*32 + (lane & 15)) * SROW + (lane >> 4) * 16);
    const uint32_t wOffBase = (uint32_t)(2*SARR +
        (warpN*64 + (lane & 7) + ((lane >> 4) & 1) * 8) * SROW + ((lane >> 3) & 1) * 16);

    auto load_tile = [&](int stage, int k0) {
        uint32_t sb = sm0 + stage * SSTAGE;
        #pragma unroll
        for (int j = 0; j < 2; j++) {
            int row = lrow[j], ch = lch[j];
            uint32_t so = (uint32_t)(row * SROW + ch * 16);
            size_t aoff = (size_t)(rowBlock + row) * lda + k0 + ch * 8;
            cpasync16(sb + so,          Agh + aoff, 16);
            cpasync16(sb + SARR + so,   Agl + aoff, 16);
            int wrow = colBlock + row;
            int sz = (wrow < N) ? 16 : 0;
            size_t woff = (wrow < N) ? ((size_t)wrow * K + k0 + ch * 8) : 0;
            cpasync16(sb + 2*SARR + so, Wgh + woff, sz);
            cpasync16(sb + 3*SARR + so, Wgl + woff, sz);
        }
        CP_COMMIT();
    };

    load_tile(0, ks);

    for (int t = 0; t < ntk; t++) {
        if (t + 1 < ntk) { load_tile((t + 1) & 1, ks + (t + 1) * 32); CP_WAIT1(); }
        else             { CP_WAIT0(); }
        __syncthreads();

        uint32_t sb = sm0 + (t & 1) * SSTAGE;
        #pragma unroll
        for (int kk = 0; kk < 2; kk++) {
            uint32_t a_h[2][4], a_l[2][4];
            #pragma unroll
            for (int mt = 0; mt < 2; mt++) {
                uint32_t ad = sb + aOffBase + (uint32_t)(mt * 16 * SROW) + kk * 32;
                LDSM_X4(a_h[mt], ad);
                LDSM_X4(a_l[mt], ad + SARR);
            }
            #pragma unroll
            for (int ng = 0; ng < 4; ng++) {
                uint32_t wd = sb + wOffBase + (uint32_t)(ng * 16 * SROW) + kk * 32;
                uint32_t b_h[4], b_l[4];
                LDSM_X4(b_h, wd);
                LDSM_X4(b_l, wd + SARR);
                #pragma unroll
                for (int p = 0; p < 2; p++) {
                    int nt = ng * 2 + p;
                    #pragma unroll
                    for (int mt = 0; mt < 2; mt++) {
                        mma_bf16(acc[mt][nt], a_h[mt], &b_h[2*p]);
                        mma_bf16(acc[mt][nt], a_h[mt], &b_l[2*p]);
                        mma_bf16(acc[mt][nt], a_l[mt], &b_h[2*p]);
                    }
                }
            }
        }
        __syncthreads();
    }

    float* Cz = C0 + (size_t)blockIdx.z * ((size_t)M * ldc);
    #pragma unroll
    for (int mt = 0; mt < 2; mt++) {
        #pragma unroll
        for (int nt = 0; nt < 8; nt++) {
            int c = colBlock + warpN * 64 + nt * 8 + tig * 2;
            if (c >= N) continue;
            #pragma unroll
            for (int half = 0; half < 2; half++) {
                int r = rowBlock + warpM * 32 + mt * 16 + grp + half * 8;
                float v0 = acc[mt][nt][half * 2 + 0];
                float v1 = acc[mt][nt][half * 2 + 1];
                if (EPI == EPI_SOFTPLUS) {
                    v0 += bias[c];
                    v1 += bias[c + 1];
                    v0 = (v0 > 0.f) ? (v0 + log1pf(expf(-v0))) : log1pf(expf(v0));
                    v1 = (v1 > 0.f) ? (v1 + log1pf(expf(-v1))) : log1pf(expf(v1));
                }
                if (EPI == EPI_SPLIT) {
                    float* dst = (c < D_INNER)
                        ? (C0 + (size_t)r * ldc + c)
                        : (C1 + (size_t)r * ldc + (c - D_INNER));
                    *(float2*)dst = make_float2(v0, v1);
                } else {
                    *(float2*)(Cz + (size_t)r * ldc + c) = make_float2(v0, v1);
                }
            }
        }
    }
}

// --------------------------- weight/src split -------------------------------
__global__ void split_kernel(const float* __restrict__ in,
                             uint32_t* __restrict__ hi, uint32_t* __restrict__ lo,
                             int npairs)
{
    int i = blockIdx.x * 256 + threadIdx.x;
    if (i >= npairs) return;
    float2 v = ((const float2*)in)[i];
    hi[i] = pack_hi(v.x, v.y);
    lo[i] = pack_lo(v.x, v.y);
}

// ------------------------- split-K reduction -------------------------------
__global__ void reduce_part_kernel()
{
    int i = blockIdx.x * 256 + threadIdx.x;
    if (i >= T_TOK * XDBL_W) return;
    float s = 0.f;
    #pragma unroll
    for (int z = 0; z < SPLITK; z++) s += g_part[(size_t)z * (T_TOK*XDBL_W) + i];
    g_xdbl[i] = s;
    split1(s, &g_xdh[i], &g_xdl[i]);
}

// --------------------- causal depthwise conv + silu ------------------------
__global__ void conv_silu_kernel(const float* __restrict__ cw,
                                 const float* __restrict__ cb)
{
    int idx = blockIdx.x * 256 + threadIdx.x;
    if (idx >= T_TOK * D_INNER) return;
    int d = idx % D_INNER;
    int t = idx / D_INNER;
    int b = t / SEQ, s = t % SEQ;
    float w0 = cw[d*4+0], w1 = cw[d*4+1], w2 = cw[d*4+2], w3 = cw[d*4+3];
    const float* col = g_xr + (size_t)(b*SEQ) * D_INNER + d;
    float acc = cb[d];
    if (s >= 3) acc = fmaf(col[(size_t)(s-3)*D_INNER], w0, acc);
    if (s >= 2) acc = fmaf(col[(size_t)(s-2)*D_INNER], w1, acc);
    if (s >= 1) acc = fmaf(col[(size_t)(s-1)*D_INNER], w2, acc);
    acc = fmaf(col[(size_t)s*D_INNER], w3, acc);
    float u = acc / (1.f + expf(-acc));   // silu
    split1(u, &g_uh[idx], &g_ul[idx]);    // fp32 u dropped; consumers use hi+lo
}

// ------------------------------ selective scan ------------------------------
#define SCH 16
#define SST 64
__global__ __launch_bounds__(256)
void scan_kernel(const float* __restrict__ A_log, const float* __restrict__ Dp)
{
    const int b = blockIdx.y;
    const int d_base = blockIdx.x * SCH;
    const int tid = threadIdx.x;
    const int ch = tid >> 4;
    const int n  = tid & 15;
    const int d  = d_base + ch;

    __shared__ float s_dt[SST][SCH];
    __shared__ float s_u [SST][SCH];
    __shared__ float s_B [SST][D_STATE];
    __shared__ float s_C [SST][D_STATE];
    __shared__ float s_y [SST][SCH];

    const float a = -expf(A_log[(size_t)d * D_STATE + n]);
    float h = 0.f;

    for (int s0 = 0; s0 < SEQ; s0 += SST) {
        for (int i = tid; i < SST*SCH; i += 256) {
            int st = i >> 4, c = i & 15;
            size_t off = (size_t)(b*SEQ + s0 + st) * D_INNER + d_base + c;
            s_dt[st][c] = g_dt[off];
            s_u [st][c] = __bfloat162float(g_uh[off]) + __bfloat162float(g_ul[off]);
        }
        for (int i = tid; i < SST*D_STATE; i += 256) {
            int st = i >> 4, nn = i & 15;
            const float* row = g_xdbl + (size_t)(b*SEQ + s0 + st) * XDBL_W;
            s_B[st][nn] = row[DT_RANK + nn];
            s_C[st][nn] = row[DT_RANK + D_STATE + nn];
        }
        __syncthreads();

        #pragma unroll 4
        for (int st = 0; st < SST; st++) {
            float dtv = s_dt[st][ch];
            float da  = __expf(dtv * a);
            float xb  = dtv * s_u[st][ch] * s_B[st][n];
            h = fmaf(da, h, xb);
            float yv = h * s_C[st][n];
            yv += __shfl_xor_sync(0xffffffffu, yv, 8, 16);
            yv += __shfl_xor_sync(0xffffffffu, yv, 4, 16);
            yv += __shfl_xor_sync(0xffffffffu, yv, 2, 16);
            yv += __shfl_xor_sync(0xffffffffu, yv, 1, 16);
            if (n == 0) s_y[st][ch] = yv;
        }
        __syncthreads();

        for (int i = tid; i < SST*SCH; i += 256) {
            int st = i >> 4, c = i & 15;
            size_t off = (size_t)(b*SEQ + s0 + st) * D_INNER + d_base + c;
            float zz = g_z[off];
            float sz = zz / (1.f + __expf(-zz));
            float yy = fmaf(Dp[d_base + c], s_u[st][c], s_y[st][c]) * sz;
            split1(yy, &g_yh[off], &g_yl[off]);
        }
        __syncthreads();
    }
}

// ------------------------------ layernorm ----------------------------------
__global__ __launch_bounds__(256)
void ln_kernel(const float* __restrict__ in, const float* __restrict__ w,
               const float* __restrict__ bb, float* __restrict__ out,
               int write_f32)
{
    const int t = blockIdx.x;
    const int tid = threadIdx.x;
    float4 v = ((const float4*)(in + (size_t)t * D_MODEL))[tid];
    __shared__ float red[9];

    float s = v.x + v.y + v.z + v.w;
    #pragma unroll
    for (int o = 16; o; o >>= 1) s += __shfl_xor_sync(~0u, s, o);
    if ((tid & 31) == 0) red[tid >> 5] = s;
    __syncthreads();
    if (tid == 0) {
        float tot = 0.f;
        #pragma unroll
        for (int i = 0; i < 8; i++) tot += red[i];
        red[8] = tot * (1.f / D_MODEL);
    }
    __syncthreads();
    const float mean = red[8];

    float dx0 = v.x - mean, dx1 = v.y - mean, dx2 = v.z - mean, dx3 = v.w - mean;
    float q = dx0*dx0 + dx1*dx1 + dx2*dx2 + dx3*dx3;
    #pragma unroll
    for (int o = 16; o; o >>= 1) q += __shfl_xor_sync(~0u, q, o);
    __syncthreads();
    if ((tid & 31) == 0) red[tid >> 5] = q;
    __syncthreads();
    if (tid == 0) {
        float tot = 0.f;
        #pragma unroll
        for (int i = 0; i < 8; i++) tot += red[i];
        red[8] = rsqrtf(tot * (1.f / D_MODEL) + 1e-5f);
    }
    __syncthreads();
    const float inv = red[8];

    float4 wv = ((const float4*)w)[tid];
    float4 bv = ((const float4*)bb)[tid];
    float4 o;
    o.x = fmaf(dx0 * inv, wv.x, bv.x);
    o.y = fmaf(dx1 * inv, wv.y, bv.y);
    o.z = fmaf(dx2 * inv, wv.z, bv.z);
    o.w = fmaf(dx3 * inv, wv.w, bv.w);
    if (write_f32)
        ((float4*)(out + (size_t)t * D_MODEL))[tid] = o;

    int pidx = t * (D_MODEL/2) + tid * 2;
    ((uint32_t*)g_xh)[pidx]     = pack_hi(o.x, o.y);
    ((uint32_t*)g_xh)[pidx + 1] = pack_hi(o.z, o.w);
    ((uint32_t*)g_xl)[pidx]     = pack_lo(o.x, o.y);
    ((uint32_t*)g_xl)[pidx + 1] = pack_lo(o.z, o.w);
}

// ------------------------------ decoder ------------------------------------
__global__ void dec_kernel(const float* __restrict__ x,
                           const float* __restrict__ dw,
                           const float* __restrict__ db,
                           float* __restrict__ out)
{
    int warp = (blockIdx.x * blockDim.x + threadIdx.x) >> 5;
    int lane = threadIdx.x & 31;
    if (warp >= T_TOK) return;
    const float* row = x + (size_t)warp * D_MODEL;
    float s = 0.f;
    for (int k = lane; k < D_MODEL; k += 32) s = fmaf(row[k], dw[k], s);
    #pragma unroll
    for (int o = 16; o; o >>= 1) s += __shfl_xor_sync(~0u, s, o);
    if (lane == 0) out[warp] = 1.f / (1.f + expf(-(s + db[0])));
}

// ------------------------------ launcher -----------------------------------
extern "C" void kernel_launch(void* const* d_in, const int* in_sizes, int n_in,
                              void* d_out, int out_size)
{
    const float* source = (const float*)d_in[0];
    const float* ipw    = (const float*)d_in[1];
    const float* cw     = (const float*)d_in[2];
    const float* cb     = (const float*)d_in[3];
    const float* xpw    = (const float*)d_in[4];
    const float* dpw    = (const float*)d_in[5];
    const float* dpb    = (const float*)d_in[6];
    const float* alog   = (const float*)d_in[7];
    const float* Dp     = (const float*)d_in[8];
    const float* opw    = (const float*)d_in[9];
    const float* lnw    = (const float*)d_in[10];
    const float* lnb    = (const float*)d_in[11];
    const float* dw     = (const float*)d_in[12];
    const float* db     = (const float*)d_in[13];
    float* out = (float*)d_out;

    float *p_xr, *p_z, *p_xdbl, *p_dt, *p_o1, *p_x, *p_part;
    cudaGetSymbolAddress((void**)&p_xr,   g_xr);
    cudaGetSymbolAddress((void**)&p_z,    g_z);
    cudaGetSymbolAddress((void**)&p_xdbl, g_xdbl);
    cudaGetSymbolAddress((void**)&p_dt,   g_dt);
    cudaGetSymbolAddress((void**)&p_o1,   g_o1);
    cudaGetSymbolAddress((void**)&p_x,    g_x);
    cudaGetSymbolAddress((void**)&p_part, g_part);

    __nv_bfloat16 *p_xh, *p_xl, *p_uh, *p_ul, *p_yh, *p_yl, *p_xdh, *p_xdl;
    cudaGetSymbolAddress((void**)&p_xh,  g_xh);
    cudaGetSymbolAddress((void**)&p_xl,  g_xl);
    cudaGetSymbolAddress((void**)&p_uh,  g_uh);
    cudaGetSymbolAddress((void**)&p_ul,  g_ul);
    cudaGetSymbolAddress((void**)&p_yh,  g_yh);
    cudaGetSymbolAddress((void**)&p_yl,  g_yl);
    cudaGetSymbolAddress((void**)&p_xdh, g_xdh);
    cudaGetSymbolAddress((void**)&p_xdl, g_xdl);

    __nv_bfloat16 *p_ipwh, *p_ipwl, *p_xpwh, *p_xpwl, *p_dpwh, *p_dpwl, *p_opwh, *p_opwl;
    cudaGetSymbolAddress((void**)&p_ipwh, g_ipwh);
    cudaGetSymbolAddress((void**)&p_ipwl, g_ipwl);
    cudaGetSymbolAddress((void**)&p_xpwh, g_xpwh);
    cudaGetSymbolAddress((void**)&p_xpwl, g_xpwl);
    cudaGetSymbolAddress((void**)&p_dpwh, g_dpwh);
    cudaGetSymbolAddress((void**)&p_dpwl, g_dpwl);
    cudaGetSymbolAddress((void**)&p_opwh, g_opwh);
    cudaGetSymbolAddress((void**)&p_opwl, g_opwl);

    cudaFuncSetAttribute(tgemm2<EPI_SPLIT>,    cudaFuncAttributeMaxDynamicSharedMemorySize, SMEM_GEMM);
    cudaFuncSetAttribute(tgemm2<EPI_NONE>,     cudaFuncAttributeMaxDynamicSharedMemorySize, SMEM_GEMM);
    cudaFuncSetAttribute(tgemm2<EPI_SOFTPLUS>, cudaFuncAttributeMaxDynamicSharedMemorySize, SMEM_GEMM);

    // per-launch weight + source splits
    {
        int np;
        np = N_LAYERS*2*D_INNER*D_MODEL/2;
        split_kernel<<<(np+255)/256, 256>>>(ipw, (uint32_t*)p_ipwh, (uint32_t*)p_ipwl, np);
        np = N_LAYERS*XDBL_W*D_INNER/2;
        split_kernel<<<(np+255)/256, 256>>>(xpw, (uint32_t*)p_xpwh, (uint32_t*)p_xpwl, np);
        np = N_LAYERS*D_INNER*DT_RANK/2;
        split_kernel<<<(np+255)/256, 256>>>(dpw, (uint32_t*)p_dpwh, (uint32_t*)p_dpwl, np);
        np = N_LAYERS*D_MODEL*D_INNER/2;
        split_kernel<<<(np+255)/256, 256>>>(opw, (uint32_t*)p_opwh, (uint32_t*)p_opwl, np);
        np = T_TOK*D_MODEL/2;
        split_kernel<<<(np+255)/256, 256>>>(source, (uint32_t*)p_xh, (uint32_t*)p_xl, np);
    }

    for (int i = 0; i < N_LAYERS; i++) {
        // 1) xz = x @ in_proj^T -> (xr | z)
        tgemm2<EPI_SPLIT><<<dim3(32, 32, 1), 256, SMEM_GEMM>>>(
            p_xh, p_xl, D_MODEL,
            p_ipwh + (size_t)i * 2*D_INNER*D_MODEL, p_ipwl + (size_t)i * 2*D_INNER*D_MODEL,
            p_xr, p_z, nullptr,
            T_TOK, 2*D_INNER, D_MODEL, D_INNER, D_MODEL);

        // 2) causal depthwise conv + bias + silu -> uh/ul
        conv_silu_kernel<<<(T_TOK*D_INNER)/256, 256>>>(
            cw + (size_t)i * D_INNER * D_CONV, cb + (size_t)i * D_INNER);

        // 3) x_dbl = u @ x_proj^T (N=96, split-K=8) + reduce (+split)
        tgemm2<EPI_NONE><<<dim3(1, 32, SPLITK), 256, SMEM_GEMM>>>(
            p_uh, p_ul, D_INNER,
            p_xpwh + (size_t)i * XDBL_W * D_INNER, p_xpwl + (size_t)i * XDBL_W * D_INNER,
            p_part, nullptr, nullptr,
            T_TOK, XDBL_W, D_INNER, XDBL_W, D_INNER / SPLITK);
        reduce_part_kernel<<<(T_TOK*XDBL_W + 255)/256, 256>>>();

        // 4) dt = softplus(dt_in @ dt_proj^T + dt_bias)
        tgemm2<EPI_SOFTPLUS><<<dim3(16, 32, 1), 256, SMEM_GEMM>>>(
            p_xdh, p_xdl, XDBL_W,
            p_dpwh + (size_t)i * D_INNER * DT_RANK, p_dpwl + (size_t)i * D_INNER * DT_RANK,
            p_dt, nullptr, dpb + (size_t)i * D_INNER,
            T_TOK, D_INNER, DT_RANK, D_INNER, DT_RANK);

        // 5) selective scan (+ D*u, * silu(z), split output)
        scan_kernel<<<dim3(D_INNER / SCH, BATCH), 256>>>(
            alog + (size_t)i * D_INNER * D_STATE, Dp + (size_t)i * D_INNER);

        // 6) out = y @ out_proj^T
        tgemm2<EPI_NONE><<<dim3(8, 32, 1), 256, SMEM_GEMM>>>(
            p_yh, p_yl, D_INNER,
            p_opwh + (size_t)i * D_MODEL * D_INNER, p_opwl + (size_t)i * D_MODEL * D_INNER,
            p_o1, nullptr, nullptr,
            T_TOK, D_MODEL, D_INNER, D_MODEL, D_INNER);

        // 7) layernorm -> xh/xl (+ fp32 g_x only on last layer for decoder)
        ln_kernel<<<T_TOK, 256>>>(p_o1, lnw + (size_t)i * D_MODEL,
                                  lnb + (size_t)i * D_MODEL, p_x,
                                  (i == N_LAYERS - 1) ? 1 : 0);
    }

    dec_kernel<<<(T_TOK * 32) / 256, 256>>>(p_x, dw, db, out);
}

// round 9
// speedup vs baseline: 1.1320x; 1.0236x over previous
#include <cuda_runtime.h>
#include <cuda_bf16.h>
#include <math.h>
#include <stdint.h>

#define D_MODEL 1024
#define D_INNER 2048
#define D_STATE 16
#define D_CONV 4
#define DT_RANK 64
#define N_LAYERS 6
#define BATCH 2
#define SEQ 2048
#define T_TOK (BATCH*SEQ)      // 4096 tokens
#define XDBL_W (DT_RANK + 2*D_STATE)   // 96
#define SPLITK 8

// ------------------------- scratch (device globals) -------------------------
__device__ float g_xr  [T_TOK * D_INNER];   // only boundary rows written now
__device__ float g_z   [T_TOK * D_INNER];
__device__ float g_xdbl[T_TOK * XDBL_W];
__device__ float g_part[SPLITK * T_TOK * XDBL_W];
__device__ float g_dt  [T_TOK * D_INNER];
__device__ float g_o1  [T_TOK * D_MODEL];
__device__ float g_x   [T_TOK * D_MODEL];

// split bf16 activations (hi/lo)
__device__ __nv_bfloat16 g_xh [T_TOK * D_MODEL],  g_xl [T_TOK * D_MODEL];
__device__ __nv_bfloat16 g_uh [T_TOK * D_INNER],  g_ul [T_TOK * D_INNER];
__device__ __nv_bfloat16 g_yh [T_TOK * D_INNER],  g_yl [T_TOK * D_INNER];
__device__ __nv_bfloat16 g_xdh[T_TOK * XDBL_W],   g_xdl[T_TOK * XDBL_W];

// split bf16 weights (per launch prep)
__device__ __nv_bfloat16 g_ipwh[N_LAYERS*2*D_INNER*D_MODEL], g_ipwl[N_LAYERS*2*D_INNER*D_MODEL];
__device__ __nv_bfloat16 g_xpwh[N_LAYERS*XDBL_W*D_INNER],    g_xpwl[N_LAYERS*XDBL_W*D_INNER];
__device__ __nv_bfloat16 g_dpwh[N_LAYERS*D_INNER*DT_RANK],   g_dpwl[N_LAYERS*D_INNER*DT_RANK];
__device__ __nv_bfloat16 g_opwh[N_LAYERS*D_MODEL*D_INNER],   g_opwl[N_LAYERS*D_MODEL*D_INNER];

// --------------------------- bf16 split helpers -----------------------------
__device__ __forceinline__ uint32_t pack_hi(float x0, float x1) {
    return (__float_as_uint(x1) & 0xFFFF0000u) | (__float_as_uint(x0) >> 16);
}
__device__ __forceinline__ uint32_t pack_lo(float x0, float x1) {
    float h0 = __uint_as_float(__float_as_uint(x0) & 0xFFFF0000u);
    float h1 = __uint_as_float(__float_as_uint(x1) & 0xFFFF0000u);
    __nv_bfloat162 t = __floats2bfloat162_rn(x0 - h0, x1 - h1);
    return *(uint32_t*)&t;
}
__device__ __forceinline__ void split1(float v, __nv_bfloat16* hi, __nv_bfloat16* lo) {
    uint16_t hb = (uint16_t)(__float_as_uint(v) >> 16);
    *(uint16_t*)hi = hb;
    float hf = __uint_as_float((uint32_t)hb << 16);
    *lo = __float2bfloat16(v - hf);
}

__device__ __forceinline__ void mma_bf16(float d[4], const uint32_t a[4],
                                         const uint32_t b[2]) {
    asm("mma.sync.aligned.m16n8k16.row.col.f32.bf16.bf16.f32 "
        "{%0,%1,%2,%3}, {%4,%5,%6,%7}, {%8,%9}, {%0,%1,%2,%3};\n"
        : "+f"(d[0]), "+f"(d[1]), "+f"(d[2]), "+f"(d[3])
        : "r"(a[0]), "r"(a[1]), "r"(a[2]), "r"(a[3]), "r"(b[0]), "r"(b[1]));
}

#define LDSM_X4(r, addr) \
    asm volatile("ldmatrix.sync.aligned.m8n8.x4.shared.b16 {%0,%1,%2,%3}, [%4];" \
        : "=r"((r)[0]), "=r"((r)[1]), "=r"((r)[2]), "=r"((r)[3]) : "r"(addr))

__device__ __forceinline__ void cpasync16(uint32_t dst, const void* src, int sz) {
    asm volatile("cp.async.cg.shared.global [%0], [%1], 16, %2;\n"
                 :: "r"(dst), "l"(src), "r"(sz) : "memory");
}
#define CP_COMMIT() asm volatile("cp.async.commit_group;\n" ::: "memory")
#define CP_WAIT0()  asm volatile("cp.async.wait_group 0;\n" ::: "memory")
#define CP_WAIT1()  asm volatile("cp.async.wait_group 1;\n" ::: "memory")

__device__ __forceinline__ uint32_t smaddr(const void* p) {
    uint32_t a;
    asm("{ .reg .u64 t; cvta.to.shared.u64 t, %1; cvt.u32.u64 %0, t; }"
        : "=r"(a) : "l"(p));
    return a;
}

// ================== warp-mma bf16x3 GEMM (2-stage, occ 2) ===================
// C[M,N] = A[M,K(lda)] @ W[N,K]^T, A/W pre-split bf16 hi/lo. 128x128 tile,
// BK=32, 256 thr (4Mx2N warps, 32x64 warp tile), 2-stage cp.async pipeline,
// ldmatrix fragments, 3-term compensated bf16 m16n8k16 MMA. Split-K via z.
// EPI_SPLIT (in_proj): xr-half tiles fuse conv+silu+split in the epilogue
// (SMEM-staged tile; rows 0..2 handled by conv_fix_kernel); z half -> g_z.
enum { EPI_NONE = 0, EPI_SPLIT = 1, EPI_SOFTPLUS = 2 };

#define SROW 80                      // smem row stride bytes (64 data + 16 pad)
#define SARR 10240                   // per-matrix smem bytes (128*80)
#define SSTAGE 40960                 // 4 matrices per stage
#define SMEM_GEMM (2*SSTAGE)         // 81920 -> 2 CTAs/SM
#define STW 132                      // staging tile row stride (floats)

template<int EPI>
__global__ __launch_bounds__(256, 2)
void tgemm2(const __nv_bfloat16* __restrict__ Agh, const __nv_bfloat16* __restrict__ Agl,
            int lda,
            const __nv_bfloat16* __restrict__ Wgh, const __nv_bfloat16* __restrict__ Wgl,
            float* __restrict__ C0, float* __restrict__ C1,
            const float* __restrict__ bias,
            const float* __restrict__ cw, const float* __restrict__ cbias,
            int M, int N, int K, int ldc, int kPerSplit)
{
    extern __shared__ uint8_t smraw[];
    uint32_t sm0 = smaddr(smraw);

    const int tid  = threadIdx.x;
    const int lane = tid & 31;
    const int wid  = tid >> 5;
    const int warpM = wid & 3;
    const int warpN = wid >> 2;
    const int grp  = lane >> 2;
    const int tig  = lane & 3;

    const int rowBlock = blockIdx.y * 128;
    const int colBlock = blockIdx.x * 128;
    const int ks = blockIdx.z * kPerSplit;
    const int ntk = kPerSplit / 32;

    float acc[2][8][4];
    #pragma unroll
    for (int mt = 0; mt < 2; mt++)
        #pragma unroll
        for (int nt = 0; nt < 8; nt++)
            #pragma unroll
            for (int q = 0; q < 4; q++) acc[mt][nt][q] = 0.f;

    int lrow[2], lch[2];
    #pragma unroll
    for (int j = 0; j < 2; j++) { int idx = tid + j*256; lrow[j] = idx >> 2; lch[j] = idx & 3; }

    const uint32_t aOffBase = (uint32_t)((warpM*32 + (lane & 15)) * SROW + (lane >> 4) * 16);
    const uint32_t wOffBase = (uint32_t)(2*SARR +
        (warpN*64 + (lane & 7) + ((lane >> 4) & 1) * 8) * SROW + ((lane >> 3) & 1) * 16);

    auto load_tile = [&](int stage, int k0) {
        uint32_t sb = sm0 + stage * SSTAGE;
        #pragma unroll
        for (int j = 0; j < 2; j++) {
            int row = lrow[j], ch = lch[j];
            uint32_t so = (uint32_t)(row * SROW + ch * 16);
            size_t aoff = (size_t)(rowBlock + row) * lda + k0 + ch * 8;
            cpasync16(sb + so,          Agh + aoff, 16);
            cpasync16(sb + SARR + so,   Agl + aoff, 16);
            int wrow = colBlock + row;
            int sz = (wrow < N) ? 16 : 0;
            size_t woff = (wrow < N) ? ((size_t)wrow * K + k0 + ch * 8) : 0;
            cpasync16(sb + 2*SARR + so, Wgh + woff, sz);
            cpasync16(sb + 3*SARR + so, Wgl + woff, sz);
        }
        CP_COMMIT();
    };

    load_tile(0, ks);

    for (int t = 0; t < ntk; t++) {
        if (t + 1 < ntk) { load_tile((t + 1) & 1, ks + (t + 1) * 32); CP_WAIT1(); }
        else             { CP_WAIT0(); }
        __syncthreads();

        uint32_t sb = sm0 + (t & 1) * SSTAGE;
        #pragma unroll
        for (int kk = 0; kk < 2; kk++) {
            uint32_t a_h[2][4], a_l[2][4];
            #pragma unroll
            for (int mt = 0; mt < 2; mt++) {
                uint32_t ad = sb + aOffBase + (uint32_t)(mt * 16 * SROW) + kk * 32;
                LDSM_X4(a_h[mt], ad);
                LDSM_X4(a_l[mt], ad + SARR);
            }
            #pragma unroll
            for (int ng = 0; ng < 4; ng++) {
                uint32_t wd = sb + wOffBase + (uint32_t)(ng * 16 * SROW) + kk * 32;
                uint32_t b_h[4], b_l[4];
                LDSM_X4(b_h, wd);
                LDSM_X4(b_l, wd + SARR);
                #pragma unroll
                for (int p = 0; p < 2; p++) {
                    int nt = ng * 2 + p;
                    #pragma unroll
                    for (int mt = 0; mt < 2; mt++) {
                        mma_bf16(acc[mt][nt], a_h[mt], &b_h[2*p]);
                        mma_bf16(acc[mt][nt], a_h[mt], &b_l[2*p]);
                        mma_bf16(acc[mt][nt], a_l[mt], &b_h[2*p]);
                    }
                }
            }
        }
        __syncthreads();
    }

    // ---------------- epilogue ----------------
    if (EPI == EPI_SPLIT && colBlock < D_INNER) {
        // xr half: stage tile in smem, fused conv + silu + bf16 split
        float* st = (float*)smraw;
        #pragma unroll
        for (int mt = 0; mt < 2; mt++) {
            #pragma unroll
            for (int nt = 0; nt < 8; nt++) {
                int cl = warpN * 64 + nt * 8 + tig * 2;
                #pragma unroll
                for (int half = 0; half < 2; half++) {
                    int rl = warpM * 32 + mt * 16 + grp + half * 8;
                    st[rl * STW + cl]     = acc[mt][nt][half * 2 + 0];
                    st[rl * STW + cl + 1] = acc[mt][nt][half * 2 + 1];
                }
            }
        }
        __syncthreads();

        const int c0 = (tid & 63) * 2;
        const int r0 = (tid >> 6) * 32;
        const int d0 = colBlock + c0;
        const float w00 = cw[d0*4+0], w01 = cw[d0*4+1], w02 = cw[d0*4+2], w03 = cw[d0*4+3];
        const float w10 = cw[d0*4+4], w11 = cw[d0*4+5], w12 = cw[d0*4+6], w13 = cw[d0*4+7];
        const float b0 = cbias[d0], b1 = cbias[d0+1];

        #pragma unroll 4
        for (int r = r0; r < r0 + 32; r++) {
            float x0 = st[r * STW + c0];
            float x1 = st[r * STW + c0 + 1];
            size_t trow = (size_t)(rowBlock + r) * D_INNER + d0;
            if (r < 3 || r >= 125) {      // boundary rows for conv_fix
                g_xr[trow]     = x0;
                g_xr[trow + 1] = x1;
            }
            if (r >= 3) {                 // full causal window inside tile
                float u0 = b0;
                u0 = fmaf(st[(r-3)*STW + c0], w00, u0);
                u0 = fmaf(st[(r-2)*STW + c0], w01, u0);
                u0 = fmaf(st[(r-1)*STW + c0], w02, u0);
                u0 = fmaf(x0, w03, u0);
                float u1 = b1;
                u1 = fmaf(st[(r-3)*STW + c0 + 1], w10, u1);
                u1 = fmaf(st[(r-2)*STW + c0 + 1], w11, u1);
                u1 = fmaf(st[(r-1)*STW + c0 + 1], w12, u1);
                u1 = fmaf(x1, w13, u1);
                u0 = u0 / (1.f + expf(-u0));
                u1 = u1 / (1.f + expf(-u1));
                ((uint32_t*)g_uh)[trow >> 1] = pack_hi(u0, u1);
                ((uint32_t*)g_ul)[trow >> 1] = pack_lo(u0, u1);
            }
        }
        return;
    }

    float* Cz = C0 + (size_t)blockIdx.z * ((size_t)M * ldc);
    #pragma unroll
    for (int mt = 0; mt < 2; mt++) {
        #pragma unroll
        for (int nt = 0; nt < 8; nt++) {
            int c = colBlock + warpN * 64 + nt * 8 + tig * 2;
            if (c >= N) continue;
            #pragma unroll
            for (int half = 0; half < 2; half++) {
                int r = rowBlock + warpM * 32 + mt * 16 + grp + half * 8;
                float v0 = acc[mt][nt][half * 2 + 0];
                float v1 = acc[mt][nt][half * 2 + 1];
                if (EPI == EPI_SOFTPLUS) {
                    v0 += bias[c];
                    v1 += bias[c + 1];
                    v0 = (v0 > 0.f) ? (v0 + log1pf(expf(-v0))) : log1pf(expf(v0));
                    v1 = (v1 > 0.f) ? (v1 + log1pf(expf(-v1))) : log1pf(expf(v1));
                }
                if (EPI == EPI_SPLIT) {
                    // z half only (xr half returned above)
                    *(float2*)(C1 + (size_t)r * ldc + (c - D_INNER)) = make_float2(v0, v1);
                } else {
                    *(float2*)(Cz + (size_t)r * ldc + c) = make_float2(v0, v1);
                }
            }
        }
    }
}

// --------------------- conv fixup (tile rows 0..2) ---------------------------
// Completes conv+silu+split for tokens with (t mod 128) < 3 using the boundary
// g_xr rows written by the in_proj epilogue.
#define FIX_ELEMS ((T_TOK/128) * 3 * D_INNER)   // 196608
__global__ void conv_fix_kernel(const float* __restrict__ cw,
                                const float* __restrict__ cb)
{
    int i = blockIdx.x * 256 + threadIdx.x;
    if (i >= FIX_ELEMS) return;
    int d  = i % D_INNER;
    int rt = i / D_INNER;          // tile*3 + r
    int tile = rt / 3, r = rt % 3;
    int t = tile * 128 + r;
    int s = t % SEQ;
    float w0 = cw[d*4+0], w1 = cw[d*4+1], w2 = cw[d*4+2], w3 = cw[d*4+3];
    float acc = cb[d];
    if (s >= 3) acc = fmaf(g_xr[(size_t)(t-3)*D_INNER + d], w0, acc);
    if (s >= 2) acc = fmaf(g_xr[(size_t)(t-2)*D_INNER + d], w1, acc);
    if (s >= 1) acc = fmaf(g_xr[(size_t)(t-1)*D_INNER + d], w2, acc);
    acc = fmaf(g_xr[(size_t)t*D_INNER + d], w3, acc);
    float u = acc / (1.f + expf(-acc));
    size_t off = (size_t)t * D_INNER + d;
    split1(u, &g_uh[off], &g_ul[off]);
}

// --------------------------- merged weight/src split ------------------------
#define SP1 (N_LAYERS*2*D_INNER*D_MODEL/2)   // 12,582,912 ipw pairs
#define SP2 (N_LAYERS*XDBL_W*D_INNER/2)      //    589,824 xpw
#define SP3 (N_LAYERS*D_INNER*DT_RANK/2)     //    393,216 dpw
#define SP4 (N_LAYERS*D_MODEL*D_INNER/2)     //  6,291,456 opw
#define SP5 (T_TOK*D_MODEL/2)                //  2,097,152 src
#define SP_TOTAL (SP1+SP2+SP3+SP4+SP5)       // 21,954,560

__global__ void split_all_kernel(const float* __restrict__ ipw,
                                 const float* __restrict__ xpw,
                                 const float* __restrict__ dpw,
                                 const float* __restrict__ opw,
                                 const float* __restrict__ src)
{
    int i = blockIdx.x * 256 + threadIdx.x;
    if (i >= SP_TOTAL) return;
    const float* in; uint32_t* hi; uint32_t* lo; int j;
    if (i < SP1)                  { in = ipw; hi = (uint32_t*)g_ipwh; lo = (uint32_t*)g_ipwl; j = i; }
    else if (i < SP1+SP2)         { in = xpw; hi = (uint32_t*)g_xpwh; lo = (uint32_t*)g_xpwl; j = i - SP1; }
    else if (i < SP1+SP2+SP3)     { in = dpw; hi = (uint32_t*)g_dpwh; lo = (uint32_t*)g_dpwl; j = i - (SP1+SP2); }
    else if (i < SP1+SP2+SP3+SP4) { in = opw; hi = (uint32_t*)g_opwh; lo = (uint32_t*)g_opwl; j = i - (SP1+SP2+SP3); }
    else                          { in = src; hi = (uint32_t*)g_xh;   lo = (uint32_t*)g_xl;   j = i - (SP1+SP2+SP3+SP4); }
    float2 v = ((const float2*)in)[j];
    hi[j] = pack_hi(v.x, v.y);
    lo[j] = pack_lo(v.x, v.y);
}

// ------------------------- split-K reduction -------------------------------
__global__ void reduce_part_kernel()
{
    int i = blockIdx.x * 256 + threadIdx.x;
    if (i >= T_TOK * XDBL_W) return;
    float s = 0.f;
    #pragma unroll
    for (int z = 0; z < SPLITK; z++) s += g_part[(size_t)z * (T_TOK*XDBL_W) + i];
    g_xdbl[i] = s;
    split1(s, &g_xdh[i], &g_xdl[i]);
}

// ------------------------------ selective scan ------------------------------
#define SCH 16
#define SST 64
__global__ __launch_bounds__(256)
void scan_kernel(const float* __restrict__ A_log, const float* __restrict__ Dp)
{
    const int b = blockIdx.y;
    const int d_base = blockIdx.x * SCH;
    const int tid = threadIdx.x;
    const int ch = tid >> 4;
    const int n  = tid & 15;
    const int d  = d_base + ch;

    __shared__ float s_dt[SST][SCH];
    __shared__ float s_u [SST][SCH];
    __shared__ float s_B [SST][D_STATE];
    __shared__ float s_C [SST][D_STATE];
    __shared__ float s_y [SST][SCH];

    const float a = -expf(A_log[(size_t)d * D_STATE + n]);
    float h = 0.f;

    for (int s0 = 0; s0 < SEQ; s0 += SST) {
        for (int i = tid; i < SST*SCH; i += 256) {
            int st = i >> 4, c = i & 15;
            size_t off = (size_t)(b*SEQ + s0 + st) * D_INNER + d_base + c;
            s_dt[st][c] = g_dt[off];
            s_u [st][c] = __bfloat162float(g_uh[off]) + __bfloat162float(g_ul[off]);
        }
        for (int i = tid; i < SST*D_STATE; i += 256) {
            int st = i >> 4, nn = i & 15;
            const float* row = g_xdbl + (size_t)(b*SEQ + s0 + st) * XDBL_W;
            s_B[st][nn] = row[DT_RANK + nn];
            s_C[st][nn] = row[DT_RANK + D_STATE + nn];
        }
        __syncthreads();

        #pragma unroll 4
        for (int st = 0; st < SST; st++) {
            float dtv = s_dt[st][ch];
            float da  = __expf(dtv * a);
            float xb  = dtv * s_u[st][ch] * s_B[st][n];
            h = fmaf(da, h, xb);
            float yv = h * s_C[st][n];
            yv += __shfl_xor_sync(0xffffffffu, yv, 8, 16);
            yv += __shfl_xor_sync(0xffffffffu, yv, 4, 16);
            yv += __shfl_xor_sync(0xffffffffu, yv, 2, 16);
            yv += __shfl_xor_sync(0xffffffffu, yv, 1, 16);
            if (n == 0) s_y[st][ch] = yv;
        }
        __syncthreads();

        for (int i = tid; i < SST*SCH; i += 256) {
            int st = i >> 4, c = i & 15;
            size_t off = (size_t)(b*SEQ + s0 + st) * D_INNER + d_base + c;
            float zz = g_z[off];
            float sz = zz / (1.f + __expf(-zz));
            float yy = fmaf(Dp[d_base + c], s_u[st][c], s_y[st][c]) * sz;
            split1(yy, &g_yh[off], &g_yl[off]);
        }
        __syncthreads();
    }
}

// ------------------------------ layernorm ----------------------------------
__global__ __launch_bounds__(256)
void ln_kernel(const float* __restrict__ in, const float* __restrict__ w,
               const float* __restrict__ bb, float* __restrict__ out,
               int write_f32)
{
    const int t = blockIdx.x;
    const int tid = threadIdx.x;
    float4 v = ((const float4*)(in + (size_t)t * D_MODEL))[tid];
    __shared__ float red[9];

    float s = v.x + v.y + v.z + v.w;
    #pragma unroll
    for (int o = 16; o; o >>= 1) s += __shfl_xor_sync(~0u, s, o);
    if ((tid & 31) == 0) red[tid >> 5] = s;
    __syncthreads();
    if (tid == 0) {
        float tot = 0.f;
        #pragma unroll
        for (int i = 0; i < 8; i++) tot += red[i];
        red[8] = tot * (1.f / D_MODEL);
    }
    __syncthreads();
    const float mean = red[8];

    float dx0 = v.x - mean, dx1 = v.y - mean, dx2 = v.z - mean, dx3 = v.w - mean;
    float q = dx0*dx0 + dx1*dx1 + dx2*dx2 + dx3*dx3;
    #pragma unroll
    for (int o = 16; o; o >>= 1) q += __shfl_xor_sync(~0u, q, o);
    __syncthreads();
    if ((tid & 31) == 0) red[tid >> 5] = q;
    __syncthreads();
    if (tid == 0) {
        float tot = 0.f;
        #pragma unroll
        for (int i = 0; i < 8; i++) tot += red[i];
        red[8] = rsqrtf(tot * (1.f / D_MODEL) + 1e-5f);
    }
    __syncthreads();
    const float inv = red[8];

    float4 wv = ((const float4*)w)[tid];
    float4 bv = ((const float4*)bb)[tid];
    float4 o;
    o.x = fmaf(dx0 * inv, wv.x, bv.x);
    o.y = fmaf(dx1 * inv, wv.y, bv.y);
    o.z = fmaf(dx2 * inv, wv.z, bv.z);
    o.w = fmaf(dx3 * inv, wv.w, bv.w);
    if (write_f32)
        ((float4*)(out + (size_t)t * D_MODEL))[tid] = o;

    int pidx = t * (D_MODEL/2) + tid * 2;
    ((uint32_t*)g_xh)[pidx]     = pack_hi(o.x, o.y);
    ((uint32_t*)g_xh)[pidx + 1] = pack_hi(o.z, o.w);
    ((uint32_t*)g_xl)[pidx]     = pack_lo(o.x, o.y);
    ((uint32_t*)g_xl)[pidx + 1] = pack_lo(o.z, o.w);
}

// ------------------------------ decoder ------------------------------------
__global__ void dec_kernel(const float* __restrict__ x,
                           const float* __restrict__ dw,
                           const float* __restrict__ db,
                           float* __restrict__ out)
{
    int warp = (blockIdx.x * blockDim.x + threadIdx.x) >> 5;
    int lane = threadIdx.x & 31;
    if (warp >= T_TOK) return;
    const float* row = x + (size_t)warp * D_MODEL;
    float s = 0.f;
    for (int k = lane; k < D_MODEL; k += 32) s = fmaf(row[k], dw[k], s);
    #pragma unroll
    for (int o = 16; o; o >>= 1) s += __shfl_xor_sync(~0u, s, o);
    if (lane == 0) out[warp] = 1.f / (1.f + expf(-(s + db[0])));
}

// ------------------------------ launcher -----------------------------------
extern "C" void kernel_launch(void* const* d_in, const int* in_sizes, int n_in,
                              void* d_out, int out_size)
{
    const float* source = (const float*)d_in[0];
    const float* ipw    = (const float*)d_in[1];
    const float* cw     = (const float*)d_in[2];
    const float* cb     = (const float*)d_in[3];
    const float* xpw    = (const float*)d_in[4];
    const float* dpw    = (const float*)d_in[5];
    const float* dpb    = (const float*)d_in[6];
    const float* alog   = (const float*)d_in[7];
    const float* Dp     = (const float*)d_in[8];
    const float* opw    = (const float*)d_in[9];
    const float* lnw    = (const float*)d_in[10];
    const float* lnb    = (const float*)d_in[11];
    const float* dw     = (const float*)d_in[12];
    const float* db     = (const float*)d_in[13];
    float* out = (float*)d_out;

    float *p_xr, *p_z, *p_xdbl, *p_dt, *p_o1, *p_x, *p_part;
    cudaGetSymbolAddress((void**)&p_xr,   g_xr);
    cudaGetSymbolAddress((void**)&p_z,    g_z);
    cudaGetSymbolAddress((void**)&p_xdbl, g_xdbl);
    cudaGetSymbolAddress((void**)&p_dt,   g_dt);
    cudaGetSymbolAddress((void**)&p_o1,   g_o1);
    cudaGetSymbolAddress((void**)&p_x,    g_x);
    cudaGetSymbolAddress((void**)&p_part, g_part);

    __nv_bfloat16 *p_xh, *p_xl, *p_uh, *p_ul, *p_yh, *p_yl, *p_xdh, *p_xdl;
    cudaGetSymbolAddress((void**)&p_xh,  g_xh);
    cudaGetSymbolAddress((void**)&p_xl,  g_xl);
    cudaGetSymbolAddress((void**)&p_uh,  g_uh);
    cudaGetSymbolAddress((void**)&p_ul,  g_ul);
    cudaGetSymbolAddress((void**)&p_yh,  g_yh);
    cudaGetSymbolAddress((void**)&p_yl,  g_yl);
    cudaGetSymbolAddress((void**)&p_xdh, g_xdh);
    cudaGetSymbolAddress((void**)&p_xdl, g_xdl);

    __nv_bfloat16 *p_ipwh, *p_ipwl, *p_xpwh, *p_xpwl, *p_dpwh, *p_dpwl, *p_opwh, *p_opwl;
    cudaGetSymbolAddress((void**)&p_ipwh, g_ipwh);
    cudaGetSymbolAddress((void**)&p_ipwl, g_ipwl);
    cudaGetSymbolAddress((void**)&p_xpwh, g_xpwh);
    cudaGetSymbolAddress((void**)&p_xpwl, g_xpwl);
    cudaGetSymbolAddress((void**)&p_dpwh, g_dpwh);
    cudaGetSymbolAddress((void**)&p_dpwl, g_dpwl);
    cudaGetSymbolAddress((void**)&p_opwh, g_opwh);
    cudaGetSymbolAddress((void**)&p_opwl, g_opwl);

    cudaFuncSetAttribute(tgemm2<EPI_SPLIT>,    cudaFuncAttributeMaxDynamicSharedMemorySize, SMEM_GEMM);
    cudaFuncSetAttribute(tgemm2<EPI_NONE>,     cudaFuncAttributeMaxDynamicSharedMemorySize, SMEM_GEMM);
    cudaFuncSetAttribute(tgemm2<EPI_SOFTPLUS>, cudaFuncAttributeMaxDynamicSharedMemorySize, SMEM_GEMM);

    // merged per-launch weight + source splits (one kernel)
    split_all_kernel<<<(SP_TOTAL + 255)/256, 256>>>(ipw, xpw, dpw, opw, source);

    for (int i = 0; i < N_LAYERS; i++) {
        const float* cwl = cw + (size_t)i * D_INNER * D_CONV;
        const float* cbl = cb + (size_t)i * D_INNER;

        // 1) xz = x @ in_proj^T -> (fused conv+silu -> uh/ul | z)
        tgemm2<EPI_SPLIT><<<dim3(32, 32, 1), 256, SMEM_GEMM>>>(
            p_xh, p_xl, D_MODEL,
            p_ipwh + (size_t)i * 2*D_INNER*D_MODEL, p_ipwl + (size_t)i * 2*D_INNER*D_MODEL,
            p_xr, p_z, nullptr, cwl, cbl,
            T_TOK, 2*D_INNER, D_MODEL, D_INNER, D_MODEL);

        // 1b) conv fixup for tile rows 0..2
        conv_fix_kernel<<<(FIX_ELEMS + 255)/256, 256>>>(cwl, cbl);

        // 2) x_dbl = u @ x_proj^T (N=96, split-K=8) + reduce (+split)
        tgemm2<EPI_NONE><<<dim3(1, 32, SPLITK), 256, SMEM_GEMM>>>(
            p_uh, p_ul, D_INNER,
            p_xpwh + (size_t)i * XDBL_W * D_INNER, p_xpwl + (size_t)i * XDBL_W * D_INNER,
            p_part, nullptr, nullptr, nullptr, nullptr,
            T_TOK, XDBL_W, D_INNER, XDBL_W, D_INNER / SPLITK);
        reduce_part_kernel<<<(T_TOK*XDBL_W + 255)/256, 256>>>();

        // 3) dt = softplus(dt_in @ dt_proj^T + dt_bias)
        tgemm2<EPI_SOFTPLUS><<<dim3(16, 32, 1), 256, SMEM_GEMM>>>(
            p_xdh, p_xdl, XDBL_W,
            p_dpwh + (size_t)i * D_INNER * DT_RANK, p_dpwl + (size_t)i * D_INNER * DT_RANK,
            p_dt, nullptr, dpb + (size_t)i * D_INNER, nullptr, nullptr,
            T_TOK, D_INNER, DT_RANK, D_INNER, DT_RANK);

        // 4) selective scan (+ D*u, * silu(z), split output)
        scan_kernel<<<dim3(D_INNER / SCH, BATCH), 256>>>(
            alog + (size_t)i * D_INNER * D_STATE, Dp + (size_t)i * D_INNER);

        // 5) out = y @ out_proj^T
        tgemm2<EPI_NONE><<<dim3(8, 32, 1), 256, SMEM_GEMM>>>(
            p_yh, p_yl, D_INNER,
            p_opwh + (size_t)i * D_MODEL * D_INNER, p_opwl + (size_t)i * D_MODEL * D_INNER,
            p_o1, nullptr, nullptr, nullptr, nullptr,
            T_TOK, D_MODEL, D_INNER, D_MODEL, D_INNER);

        // 6) layernorm -> xh/xl (+ fp32 g_x only on last layer for decoder)
        ln_kernel<<<T_TOK, 256>>>(p_o1, lnw + (size_t)i * D_MODEL,
                                  lnb + (size_t)i * D_MODEL, p_x,
                                  (i == N_LAYERS - 1) ? 1 : 0);
    }

    dec_kernel<<<(T_TOK * 32) / 256, 256>>>(p_x, dw, db, out);
}